// round 2
// baseline (speedup 1.0000x reference)
#include <cuda_runtime.h>
#include <math.h>

#define NN 50000
#define EE 800000
#define GG 512
#define DD 128

// ---------------- scratch (device globals; no allocations) ----------------
__device__ float d_Q[NN * DD];
__device__ float d_Kf[NN * DD];
__device__ float d_Vf[NN * DD];
__device__ float d_H[NN * DD];       // layer-0 output / layer-1 input
__device__ float d_A[EE * 2];        // alpha, then ex (softmax numerator)
__device__ float d_AMAX[NN * 2];
__device__ float d_DEN[NN * 2];
__device__ float d_GSUM[GG * DD];
__device__ float d_GCNT[GG];

// ---------------- init kernels ----------------
__global__ void k_init_nd(int n2) {
    int i = blockIdx.x * blockDim.x + threadIdx.x;
    if (i < n2) {
        d_AMAX[i] = __int_as_float(0xff800000);  // -inf
        d_DEN[i] = 0.0f;
    }
}

__global__ void k_init_pool() {
    int i = blockIdx.x * blockDim.x + threadIdx.x;
    if (i < GG * DD) d_GSUM[i] = 0.0f;
    if (i < GG) d_GCNT[i] = 0.0f;
}

// ---------------- fused QKV+skip GEMM: Y = X @ W^T + b ----------------
// blockIdx.y selects which of 4 weight matrices (q,k,v,skip).
// Tile: 64 rows x 128 outs, K=128 full. 256 threads, 8x4 microtile.
// smem: Xs[64][128], Wt[128][132] (W transposed, padded), bs[128].
#define GEMM_SMEM_FLOATS (64 * 128 + 128 * 132 + 128)
extern __shared__ float s_gemm[];

__global__ void k_gemm4(const float* __restrict__ Xext, int use_ext, int n,
                        const float* __restrict__ Wq, const float* __restrict__ bq,
                        const float* __restrict__ Wk, const float* __restrict__ bk,
                        const float* __restrict__ Wv, const float* __restrict__ bv,
                        const float* __restrict__ Wsk, const float* __restrict__ bsk,
                        float* __restrict__ Yskip) {
    float* Xs = s_gemm;                 // 64*128
    float* Wt = s_gemm + 64 * 128;      // 128*132
    float* bs = Wt + 128 * 132;         // 128

    const float* X = use_ext ? Xext : d_H;
    const float* W;
    const float* b;
    float* Y;
    int m = blockIdx.y;
    if (m == 0)      { W = Wq;  b = bq;  Y = d_Q;  }
    else if (m == 1) { W = Wk;  b = bk;  Y = d_Kf; }
    else if (m == 2) { W = Wv;  b = bv;  Y = d_Vf; }
    else             { W = Wsk; b = bsk; Y = Yskip ? Yskip : d_H; }

    int tid = threadIdx.x;
    int row0 = blockIdx.x * 64;

    // load X tile (float4-vectorized, zero-pad OOB rows)
    for (int i = tid; i < 64 * 32; i += 256) {
        int r = i >> 5, c = i & 31;
        float4 v = make_float4(0.f, 0.f, 0.f, 0.f);
        if (row0 + r < n)
            v = ((const float4*)X)[(long)(row0 + r) * 32 + c];
        ((float4*)(Xs + r * 128))[c] = v;
    }
    // load W transposed: Wt[k][o] = W[o][k]
    for (int i = tid; i < 128 * 32; i += 256) {
        int o = i >> 5, k4 = i & 31;
        float4 w = ((const float4*)W)[o * 32 + k4];
        Wt[(k4 * 4 + 0) * 132 + o] = w.x;
        Wt[(k4 * 4 + 1) * 132 + o] = w.y;
        Wt[(k4 * 4 + 2) * 132 + o] = w.z;
        Wt[(k4 * 4 + 3) * 132 + o] = w.w;
    }
    if (tid < 128) bs[tid] = b[tid];
    __syncthreads();

    int tx = tid & 31;   // output-col group (4 cols)
    int ty = tid >> 5;   // row group (8 rows)
    float acc[8][4];
#pragma unroll
    for (int r = 0; r < 8; r++)
#pragma unroll
        for (int c = 0; c < 4; c++) acc[r][c] = 0.f;

#pragma unroll 4
    for (int k = 0; k < 128; k++) {
        float4 w = *(const float4*)&Wt[k * 132 + tx * 4];
#pragma unroll
        for (int r = 0; r < 8; r++) {
            float xv = Xs[(ty * 8 + r) * 128 + k];   // warp-broadcast
            acc[r][0] += xv * w.x;
            acc[r][1] += xv * w.y;
            acc[r][2] += xv * w.z;
            acc[r][3] += xv * w.w;
        }
    }

    float4 bb = *(const float4*)&bs[tx * 4];
#pragma unroll
    for (int r = 0; r < 8; r++) {
        int row = row0 + ty * 8 + r;
        if (row < n) {
            float4 o4 = make_float4(acc[r][0] + bb.x, acc[r][1] + bb.y,
                                    acc[r][2] + bb.z, acc[r][3] + bb.w);
            ((float4*)Y)[(long)row * 32 + tx] = o4;
        }
    }
}

// ---------------- edge pass 1: alpha + segment max ----------------
// warp per edge; lanes 0-15 = head 0 (ch 0..63), lanes 16-31 = head 1.
__global__ void k_edge_alpha(const int* __restrict__ src, const int* __restrict__ dst,
                             const float* __restrict__ eattr,
                             const float* __restrict__ We, int E) {
    int e = blockIdx.x * 8 + (threadIdx.x >> 5);
    if (e >= E) return;
    int lane = threadIdx.x & 31;
    int s = __ldg(&src[e]);
    int d = __ldg(&dst[e]);
    float ea = __ldg(&eattr[e]);

    float4 q4 = __ldg((const float4*)&d_Q[(long)d * DD] + lane);
    float4 k4 = __ldg((const float4*)&d_Kf[(long)s * DD] + lane);
    float4 we = __ldg((const float4*)We + lane);

    float p = q4.x * (k4.x + ea * we.x) + q4.y * (k4.y + ea * we.y) +
              q4.z * (k4.z + ea * we.z) + q4.w * (k4.w + ea * we.w);
    p += __shfl_xor_sync(0xffffffffu, p, 8);
    p += __shfl_xor_sync(0xffffffffu, p, 4);
    p += __shfl_xor_sync(0xffffffffu, p, 2);
    p += __shfl_xor_sync(0xffffffffu, p, 1);

    if ((lane & 15) == 0) {
        int h = lane >> 4;
        float a = p * 0.125f;  // 1/sqrt(64)
        d_A[(long)e * 2 + h] = a;
        float* addr = &d_AMAX[(long)d * 2 + h];
        // float atomic max via int/uint ordering trick
        if (a >= 0.f)
            atomicMax((int*)addr, __float_as_int(a));
        else
            atomicMin((unsigned int*)addr, (unsigned int)__float_as_int(a));
    }
}

// ---------------- edge pass 2: exp + segment sum ----------------
__global__ void k_edge_exp(const int* __restrict__ dst, int E) {
    int t = blockIdx.x * blockDim.x + threadIdx.x;
    if (t >= 2 * E) return;
    int e = t >> 1, h = t & 1;
    int d = __ldg(&dst[e]);
    float ex = __expf(d_A[t] - d_AMAX[(long)d * 2 + h]);
    d_A[t] = ex;
    atomicAdd(&d_DEN[(long)d * 2 + h], ex);
}

// ---------------- edge pass 3: weighted message scatter ----------------
__global__ void k_edge_msg(const int* __restrict__ src, const int* __restrict__ dst,
                           const float* __restrict__ eattr,
                           const float* __restrict__ We, int E,
                           int use_dout, float* __restrict__ dout) {
    int e = blockIdx.x * 8 + (threadIdx.x >> 5);
    if (e >= E) return;
    int lane = threadIdx.x & 31;
    int s = __ldg(&src[e]);
    int d = __ldg(&dst[e]);
    float ea = __ldg(&eattr[e]);
    int h = lane >> 4;

    float coef = d_A[(long)e * 2 + h] / (d_DEN[(long)d * 2 + h] + 1e-16f);

    float4 v4 = __ldg((const float4*)&d_Vf[(long)s * DD] + lane);
    float4 we = __ldg((const float4*)We + lane);
    float mx = (v4.x + ea * we.x) * coef;
    float my = (v4.y + ea * we.y) * coef;
    float mz = (v4.z + ea * we.z) * coef;
    float mw = (v4.w + ea * we.w) * coef;

    float* out = use_dout ? dout : d_H;
    float* p = &out[(long)d * DD + lane * 4];
    asm volatile("red.global.add.v4.f32 [%0], {%1,%2,%3,%4};"
                 :: "l"(p), "f"(mx), "f"(my), "f"(mz), "f"(mw)
                 : "memory");
}

// ---------------- relu on layer-0 output ----------------
__global__ void k_relu(int n) {
    int i = blockIdx.x * blockDim.x + threadIdx.x;
    if (i < n) d_H[i] = fmaxf(d_H[i], 0.0f);
}

// ---------------- mean pool (sums + counts) ----------------
__global__ void k_pool(const float* __restrict__ hout, const int* __restrict__ batch, int n) {
    int node = blockIdx.x * 8 + (threadIdx.x >> 5);
    if (node >= n) return;
    int lane = threadIdx.x & 31;
    int g = __ldg(&batch[node]);
    float4 v = __ldg((const float4*)&hout[(long)node * DD] + lane);
    float* p = &d_GSUM[(long)g * DD + lane * 4];
    asm volatile("red.global.add.v4.f32 [%0], {%1,%2,%3,%4};"
                 :: "l"(p), "f"(v.x), "f"(v.y), "f"(v.z), "f"(v.w)
                 : "memory");
    if (lane == 0) atomicAdd(&d_GCNT[g], 1.0f);
}

// ---------------- MLP head: 128 -> 64 -> 32 -> 16 ----------------
__global__ void k_mlp(const float* __restrict__ W1, const float* __restrict__ b1,
                      const float* __restrict__ W2, const float* __restrict__ b2,
                      const float* __restrict__ W3, const float* __restrict__ b3,
                      float* __restrict__ out, int n_nodes) {
    __shared__ float g[128];
    __shared__ float h1[64];
    __shared__ float h2[32];
    int gr = blockIdx.x;
    int t = threadIdx.x;
    float cnt = fmaxf(d_GCNT[gr], 1.0f);
    if (t < 128) g[t] = d_GSUM[gr * 128 + t] / cnt;
    __syncthreads();
    if (t < 64) {
        float s = b1[t];
        for (int k = 0; k < 128; k++) s += W1[t * 128 + k] * g[k];
        h1[t] = fmaxf(s, 0.0f);
    }
    __syncthreads();
    if (t < 32) {
        float s = b2[t];
        for (int k = 0; k < 64; k++) s += W2[t * 64 + k] * h1[k];
        h2[t] = fmaxf(s, 0.0f);
    }
    __syncthreads();
    if (t < 16) {
        float s = b3[t];
        for (int k = 0; k < 32; k++) s += W3[t * 32 + k] * h2[k];
        out[(long)n_nodes * 128 + gr * 16 + t] = s;
    }
}

// ---------------- launcher ----------------
extern "C" void kernel_launch(void* const* d_in, const int* in_sizes, int n_in,
                              void* d_out, int out_size) {
    const float* x      = (const float*)d_in[0];
    const int*   ei     = (const int*)d_in[1];
    const int*   batch  = (const int*)d_in[2];
    const float* eattr  = (const float*)d_in[3];

    const float* Wq0 = (const float*)d_in[4];
    const float* bq0 = (const float*)d_in[5];
    const float* Wk0 = (const float*)d_in[6];
    const float* bk0 = (const float*)d_in[7];
    const float* Wv0 = (const float*)d_in[8];
    const float* bv0 = (const float*)d_in[9];
    const float* We0 = (const float*)d_in[10];
    const float* Ws0 = (const float*)d_in[11];
    const float* bs0 = (const float*)d_in[12];

    const float* Wq1 = (const float*)d_in[13];
    const float* bq1 = (const float*)d_in[14];
    const float* Wk1 = (const float*)d_in[15];
    const float* bk1 = (const float*)d_in[16];
    const float* Wv1 = (const float*)d_in[17];
    const float* bv1 = (const float*)d_in[18];
    const float* We1 = (const float*)d_in[19];
    const float* Ws1 = (const float*)d_in[20];
    const float* bs1 = (const float*)d_in[21];

    const float* W1 = (const float*)d_in[22];
    const float* b1 = (const float*)d_in[23];
    const float* W2 = (const float*)d_in[24];
    const float* b2 = (const float*)d_in[25];
    const float* W3 = (const float*)d_in[26];
    const float* b3 = (const float*)d_in[27];

    int n = in_sizes[2];        // num nodes
    int E = in_sizes[3];        // num edges
    float* out = (float*)d_out;

    const int smem = GEMM_SMEM_FLOATS * sizeof(float);
    cudaFuncSetAttribute(k_gemm4, cudaFuncAttributeMaxDynamicSharedMemorySize, smem);

    const int* src = ei;
    const int* dst = ei + E;

    dim3 ggemm((n + 63) / 64, 4);
    int eb = (E + 7) / 8;           // warp-per-edge blocks (256 thr = 8 edges)
    int xb = (2 * E + 255) / 256;

    // ---- layer 0 (skip GEMM writes d_H; messages red-add into d_H) ----
    k_init_nd<<<(n * 2 + 255) / 256, 256>>>(n * 2);
    k_gemm4<<<ggemm, 256, smem>>>(x, 1, n, Wq0, bq0, Wk0, bk0, Wv0, bv0, Ws0, bs0, nullptr);
    k_edge_alpha<<<eb, 256>>>(src, dst, eattr, We0, E);
    k_edge_exp<<<xb, 256>>>(dst, E);
    k_edge_msg<<<eb, 256>>>(src, dst, eattr, We0, E, 0, nullptr);
    k_relu<<<(n * 128 + 255) / 256, 256>>>(n * 128);

    // ---- layer 1 (skip + messages written straight into d_out) ----
    k_init_nd<<<(n * 2 + 255) / 256, 256>>>(n * 2);
    k_gemm4<<<ggemm, 256, smem>>>(nullptr, 0, n, Wq1, bq1, Wk1, bk1, Wv1, bv1, Ws1, bs1, out);
    k_edge_alpha<<<eb, 256>>>(src, dst, eattr, We1, E);
    k_edge_exp<<<xb, 256>>>(dst, E);
    k_edge_msg<<<eb, 256>>>(src, dst, eattr, We1, E, 1, out);

    // ---- pooling + MLP head ----
    k_init_pool<<<(GG * DD + 255) / 256, 256>>>();
    k_pool<<<(n + 7) / 8, 256>>>(out, batch, n);
    k_mlp<<<GG, 128>>>(W1, b1, W2, b2, W3, b3, out, n);
}

// round 4
// speedup vs baseline: 1.2493x; 1.2493x over previous
#include <cuda_runtime.h>
#include <cuda_bf16.h>
#include <math.h>
#include <stdint.h>

#define NN 50000
#define EE 800000
#define GG 512
#define DD 128

// ---------------- scratch (device globals; no allocations) ----------------
__device__ float d_Q[NN * DD];
__device__ float d_Kf[NN * DD];
__device__ float d_Vf[NN * DD];
__device__ float d_H[NN * DD];       // layer-0 output / layer-1 input
__device__ float d_A[EE * 2];        // alpha, then ex (softmax numerator)
__device__ float d_AMAX[NN * 2];
__device__ float d_DEN[NN * 2];
__device__ float d_GSUM[GG * DD];
__device__ float d_GCNT[GG];

// ---------------- helpers ----------------
__device__ __forceinline__ uint32_t smem_u32(const void* p) {
    uint32_t a;
    asm("{ .reg .u64 t; cvta.to.shared.u64 t, %1; cvt.u32.u64 %0, t; }" : "=r"(a) : "l"(p));
    return a;
}

#define LDSM_X4(r, addr)                                                      \
    asm volatile("ldmatrix.sync.aligned.m8n8.x4.shared.b16 {%0,%1,%2,%3}, [%4];" \
                 : "=r"((r)[0]), "=r"((r)[1]), "=r"((r)[2]), "=r"((r)[3])     \
                 : "r"(addr))

__device__ __forceinline__ void mma16816(float* c, const uint32_t* a,
                                         uint32_t b0, uint32_t b1) {
    asm volatile(
        "mma.sync.aligned.m16n8k16.row.col.f32.bf16.bf16.f32 "
        "{%0,%1,%2,%3}, {%4,%5,%6,%7}, {%8,%9}, {%0,%1,%2,%3};"
        : "+f"(c[0]), "+f"(c[1]), "+f"(c[2]), "+f"(c[3])
        : "r"(a[0]), "r"(a[1]), "r"(a[2]), "r"(a[3]), "r"(b0), "r"(b1));
}

// ---------------- tensor-core GEMM via mma.sync (bf16 3-split) ----------------
// Y_m = X @ Wm^T + bm for m in {q,k,v,skip}. Block: 128 rows x 128 outs, K=128.
// smem: padded rows of 136 bf16 (272B) -> conflict-free ldmatrix, no swizzle.
#define ROWB 272                         // bytes per smem row (128 bf16 + 8 pad)
#define SA_HI 0
#define SA_LO (SA_HI + 128 * ROWB)       // 34816
#define SW_HI (SA_LO + 128 * ROWB)
#define SW_LO (SW_HI + 128 * ROWB)
#define SBIAS (SW_LO + 128 * ROWB)       // 512 floats
#define GSM_TOTAL (SBIAS + 2048)         // 141312 B

__global__ void __launch_bounds__(256, 1)
k_gemm_mma(const float* __restrict__ Xext, int use_ext, int relu_in, int n,
           const float* __restrict__ Wq, const float* __restrict__ bq,
           const float* __restrict__ Wk, const float* __restrict__ bk,
           const float* __restrict__ Wv, const float* __restrict__ bv,
           const float* __restrict__ Wsk, const float* __restrict__ bsk,
           float* __restrict__ Yskip) {
    extern __shared__ char smem[];
    const uint32_t sb = smem_u32(smem);
    const int tid = threadIdx.x;
    const int wid = tid >> 5;
    const int lane = tid & 31;
    const int row0 = blockIdx.x * 128;
    const float* X = use_ext ? Xext : d_H;
    float* s_bias = (float*)(smem + SBIAS);

    if (tid < 128) {
        s_bias[tid]       = bq[tid];
        s_bias[128 + tid] = bk[tid];
        s_bias[256 + tid] = bv[tid];
        s_bias[384 + tid] = bsk[tid];
    }

    // ---- A fill: fp32 -> bf16 hi/lo ----
    for (int idx = tid; idx < 128 * 64; idx += 256) {
        int r = idx >> 6, p = idx & 63;          // p: float2 index
        int row = row0 + r;
        float2 v = make_float2(0.f, 0.f);
        if (row < n) v = ((const float2*)X)[(long)row * 64 + p];
        if (relu_in) { v.x = fmaxf(v.x, 0.f); v.y = fmaxf(v.y, 0.f); }
        __nv_bfloat16 h0 = __float2bfloat16(v.x);
        __nv_bfloat16 h1 = __float2bfloat16(v.y);
        __nv_bfloat16 l0 = __float2bfloat16(v.x - __bfloat162float(h0));
        __nv_bfloat16 l1 = __float2bfloat16(v.y - __bfloat162float(h1));
        __nv_bfloat162 hh; hh.x = h0; hh.y = h1;
        __nv_bfloat162 ll; ll.x = l0; ll.y = l1;
        *(__nv_bfloat162*)(smem + SA_HI + r * ROWB + p * 4) = hh;
        *(__nv_bfloat162*)(smem + SA_LO + r * ROWB + p * 4) = ll;
    }
    __syncthreads();

    const int wm = wid & 3;     // m group: rows wm*32
    const int wn = wid >> 2;    // n group: cols wn*64

    // precomputed ldmatrix lane offsets
    const int a_row = wm * 32 + (lane & 15);
    const int a_colb = ((lane >> 4) * 8) * 2;             // byte offset in row
    const int b_row_in_q = ((lane >> 4) & 1) * 8 + (lane & 7);
    const int b_colb = (((lane >> 3) & 1) * 8) * 2;

    const float* Wm_[4] = {Wq, Wk, Wv, Wsk};
    float* Y_[4] = {d_Q, d_Kf, d_Vf, Yskip ? Yskip : d_H};

    for (int m = 0; m < 4; m++) {
        // ---- W fill: fp32 -> bf16 hi/lo ----
        const float* Wm = Wm_[m];
        for (int idx = tid; idx < 128 * 64; idx += 256) {
            int o = idx >> 6, p = idx & 63;
            float2 v = ((const float2*)Wm)[(long)o * 64 + p];
            __nv_bfloat16 h0 = __float2bfloat16(v.x);
            __nv_bfloat16 h1 = __float2bfloat16(v.y);
            __nv_bfloat16 l0 = __float2bfloat16(v.x - __bfloat162float(h0));
            __nv_bfloat16 l1 = __float2bfloat16(v.y - __bfloat162float(h1));
            __nv_bfloat162 hh; hh.x = h0; hh.y = h1;
            __nv_bfloat162 ll; ll.x = l0; ll.y = l1;
            *(__nv_bfloat162*)(smem + SW_HI + o * ROWB + p * 4) = hh;
            *(__nv_bfloat162*)(smem + SW_LO + o * ROWB + p * 4) = ll;
        }
        __syncthreads();

        float acc[2][8][4];
#pragma unroll
        for (int i = 0; i < 2; i++)
#pragma unroll
            for (int j = 0; j < 8; j++)
#pragma unroll
                for (int c = 0; c < 4; c++) acc[i][j][c] = 0.f;

        // 3 splits: (Ahi,Whi), (Ahi,Wlo), (Alo,Whi)
#pragma unroll
        for (int split = 0; split < 3; split++) {
            uint32_t Ab = sb + ((split == 2) ? SA_LO : SA_HI);
            uint32_t Bb = sb + ((split == 1) ? SW_LO : SW_HI);
#pragma unroll
            for (int ks = 0; ks < 8; ks++) {
                uint32_t a0[4], a1[4];
                uint32_t aaddr = Ab + a_row * ROWB + ks * 32 + a_colb;
                LDSM_X4(a0, aaddr);
                LDSM_X4(a1, aaddr + 16 * ROWB);
#pragma unroll
                for (int q = 0; q < 4; q++) {
                    uint32_t b[4];
                    uint32_t baddr = Bb + (wn * 64 + q * 16 + b_row_in_q) * ROWB
                                     + ks * 32 + b_colb;
                    LDSM_X4(b, baddr);
                    mma16816(acc[0][2 * q],     a0, b[0], b[1]);
                    mma16816(acc[0][2 * q + 1], a0, b[2], b[3]);
                    mma16816(acc[1][2 * q],     a1, b[0], b[1]);
                    mma16816(acc[1][2 * q + 1], a1, b[2], b[3]);
                }
            }
        }

        // ---- epilogue: acc + bias -> global ----
        float* Y = Y_[m];
#pragma unroll
        for (int tm = 0; tm < 2; tm++) {
#pragma unroll
            for (int tn = 0; tn < 8; tn++) {
                int col = wn * 64 + tn * 8 + (lane & 3) * 2;
                float bx = s_bias[m * 128 + col];
                float by = s_bias[m * 128 + col + 1];
                int r1 = row0 + wm * 32 + tm * 16 + (lane >> 2);
                if (r1 < n) {
                    float2 o1 = make_float2(acc[tm][tn][0] + bx, acc[tm][tn][1] + by);
                    *(float2*)&Y[(long)r1 * 128 + col] = o1;
                }
                int r2 = r1 + 8;
                if (r2 < n) {
                    float2 o2 = make_float2(acc[tm][tn][2] + bx, acc[tm][tn][3] + by);
                    *(float2*)&Y[(long)r2 * 128 + col] = o2;
                }
            }
        }
        __syncthreads();   // next mat's W fill must not race this mat's reads
    }
}

// ---------------- init kernels ----------------
__global__ void k_init_nd(int n2) {
    int i = blockIdx.x * blockDim.x + threadIdx.x;
    if (i < n2) {
        d_AMAX[i] = __int_as_float(0xff800000);  // -inf
        d_DEN[i] = 0.0f;
    }
}

__global__ void k_init_pool() {
    int i = blockIdx.x * blockDim.x + threadIdx.x;
    if (i < GG * DD) d_GSUM[i] = 0.0f;
    if (i < GG) d_GCNT[i] = 0.0f;
}

// ---------------- edge pass 1: alpha + segment max ----------------
__global__ void k_edge_alpha(const int* __restrict__ src, const int* __restrict__ dst,
                             const float* __restrict__ eattr,
                             const float* __restrict__ We, int E) {
    int e = blockIdx.x * 8 + (threadIdx.x >> 5);
    if (e >= E) return;
    int lane = threadIdx.x & 31;
    int s = __ldg(&src[e]);
    int d = __ldg(&dst[e]);
    float ea = __ldg(&eattr[e]);

    float4 q4 = __ldg((const float4*)&d_Q[(long)d * DD] + lane);
    float4 k4 = __ldg((const float4*)&d_Kf[(long)s * DD] + lane);
    float4 we = __ldg((const float4*)We + lane);

    float p = q4.x * (k4.x + ea * we.x) + q4.y * (k4.y + ea * we.y) +
              q4.z * (k4.z + ea * we.z) + q4.w * (k4.w + ea * we.w);
    p += __shfl_xor_sync(0xffffffffu, p, 8);
    p += __shfl_xor_sync(0xffffffffu, p, 4);
    p += __shfl_xor_sync(0xffffffffu, p, 2);
    p += __shfl_xor_sync(0xffffffffu, p, 1);

    if ((lane & 15) == 0) {
        int h = lane >> 4;
        float a = p * 0.125f;  // 1/sqrt(64)
        d_A[(long)e * 2 + h] = a;
        float* addr = &d_AMAX[(long)d * 2 + h];
        if (a >= 0.f)
            atomicMax((int*)addr, __float_as_int(a));
        else
            atomicMin((unsigned int*)addr, (unsigned int)__float_as_int(a));
    }
}

// ---------------- edge pass 2: exp + segment sum ----------------
__global__ void k_edge_exp(const int* __restrict__ dst, int E) {
    int t = blockIdx.x * blockDim.x + threadIdx.x;
    if (t >= 2 * E) return;
    int e = t >> 1, h = t & 1;
    int d = __ldg(&dst[e]);
    float ex = __expf(d_A[t] - d_AMAX[(long)d * 2 + h]);
    d_A[t] = ex;
    atomicAdd(&d_DEN[(long)d * 2 + h], ex);
}

// ---------------- edge pass 3: weighted message scatter ----------------
__global__ void k_edge_msg(const int* __restrict__ src, const int* __restrict__ dst,
                           const float* __restrict__ eattr,
                           const float* __restrict__ We, int E,
                           int use_dout, float* __restrict__ dout) {
    int e = blockIdx.x * 8 + (threadIdx.x >> 5);
    if (e >= E) return;
    int lane = threadIdx.x & 31;
    int s = __ldg(&src[e]);
    int d = __ldg(&dst[e]);
    float ea = __ldg(&eattr[e]);
    int h = lane >> 4;

    float coef = d_A[(long)e * 2 + h] / (d_DEN[(long)d * 2 + h] + 1e-16f);

    float4 v4 = __ldg((const float4*)&d_Vf[(long)s * DD] + lane);
    float4 we = __ldg((const float4*)We + lane);
    float mx = (v4.x + ea * we.x) * coef;
    float my = (v4.y + ea * we.y) * coef;
    float mz = (v4.z + ea * we.z) * coef;
    float mw = (v4.w + ea * we.w) * coef;

    float* out = use_dout ? dout : d_H;
    float* p = &out[(long)d * DD + lane * 4];
    asm volatile("red.global.add.v4.f32 [%0], {%1,%2,%3,%4};"
                 :: "l"(p), "f"(mx), "f"(my), "f"(mz), "f"(mw)
                 : "memory");
}

// ---------------- mean pool (sums + counts) ----------------
__global__ void k_pool(const float* __restrict__ hout, const int* __restrict__ batch, int n) {
    int node = blockIdx.x * 8 + (threadIdx.x >> 5);
    if (node >= n) return;
    int lane = threadIdx.x & 31;
    int g = __ldg(&batch[node]);
    float4 v = __ldg((const float4*)&hout[(long)node * DD] + lane);
    float* p = &d_GSUM[(long)g * DD + lane * 4];
    asm volatile("red.global.add.v4.f32 [%0], {%1,%2,%3,%4};"
                 :: "l"(p), "f"(v.x), "f"(v.y), "f"(v.z), "f"(v.w)
                 : "memory");
    if (lane == 0) atomicAdd(&d_GCNT[g], 1.0f);
}

// ---------------- MLP head: 128 -> 64 -> 32 -> 16 ----------------
__global__ void k_mlp(const float* __restrict__ W1, const float* __restrict__ b1,
                      const float* __restrict__ W2, const float* __restrict__ b2,
                      const float* __restrict__ W3, const float* __restrict__ b3,
                      float* __restrict__ out, int n_nodes) {
    __shared__ float g[128];
    __shared__ float h1[64];
    __shared__ float h2[32];
    int gr = blockIdx.x;
    int t = threadIdx.x;
    float cnt = fmaxf(d_GCNT[gr], 1.0f);
    if (t < 128) g[t] = d_GSUM[gr * 128 + t] / cnt;
    __syncthreads();
    if (t < 64) {
        float s = b1[t];
        for (int k = 0; k < 128; k++) s += W1[t * 128 + k] * g[k];
        h1[t] = fmaxf(s, 0.0f);
    }
    __syncthreads();
    if (t < 32) {
        float s = b2[t];
        for (int k = 0; k < 64; k++) s += W2[t * 64 + k] * h1[k];
        h2[t] = fmaxf(s, 0.0f);
    }
    __syncthreads();
    if (t < 16) {
        float s = b3[t];
        for (int k = 0; k < 32; k++) s += W3[t * 32 + k] * h2[k];
        out[(long)n_nodes * 128 + gr * 16 + t] = s;
    }
}

// ---------------- launcher ----------------
extern "C" void kernel_launch(void* const* d_in, const int* in_sizes, int n_in,
                              void* d_out, int out_size) {
    const float* x      = (const float*)d_in[0];
    const int*   ei     = (const int*)d_in[1];
    const int*   batch  = (const int*)d_in[2];
    const float* eattr  = (const float*)d_in[3];

    const float* Wq0 = (const float*)d_in[4];
    const float* bq0 = (const float*)d_in[5];
    const float* Wk0 = (const float*)d_in[6];
    const float* bk0 = (const float*)d_in[7];
    const float* Wv0 = (const float*)d_in[8];
    const float* bv0 = (const float*)d_in[9];
    const float* We0 = (const float*)d_in[10];
    const float* Ws0 = (const float*)d_in[11];
    const float* bs0 = (const float*)d_in[12];

    const float* Wq1 = (const float*)d_in[13];
    const float* bq1 = (const float*)d_in[14];
    const float* Wk1 = (const float*)d_in[15];
    const float* bk1 = (const float*)d_in[16];
    const float* Wv1 = (const float*)d_in[17];
    const float* bv1 = (const float*)d_in[18];
    const float* We1 = (const float*)d_in[19];
    const float* Ws1 = (const float*)d_in[20];
    const float* bs1 = (const float*)d_in[21];

    const float* W1 = (const float*)d_in[22];
    const float* b1 = (const float*)d_in[23];
    const float* W2 = (const float*)d_in[24];
    const float* b2 = (const float*)d_in[25];
    const float* W3 = (const float*)d_in[26];
    const float* b3 = (const float*)d_in[27];

    int n = in_sizes[2];        // num nodes
    int E = in_sizes[3];        // num edges
    float* out = (float*)d_out;

    cudaFuncSetAttribute(k_gemm_mma, cudaFuncAttributeMaxDynamicSharedMemorySize, GSM_TOTAL);

    const int* src = ei;
    const int* dst = ei + E;

    int gb = (n + 127) / 128;
    int eb = (E + 7) / 8;           // warp-per-edge blocks (256 thr = 8 edges)
    int xb = (2 * E + 255) / 256;

    // ---- layer 0 (skip GEMM writes d_H; messages red-add into d_H) ----
    k_init_nd<<<(n * 2 + 255) / 256, 256>>>(n * 2);
    k_gemm_mma<<<gb, 256, GSM_TOTAL>>>(x, 1, 0, n, Wq0, bq0, Wk0, bk0, Wv0, bv0, Ws0, bs0, nullptr);
    k_edge_alpha<<<eb, 256>>>(src, dst, eattr, We0, E);
    k_edge_exp<<<xb, 256>>>(dst, E);
    k_edge_msg<<<eb, 256>>>(src, dst, eattr, We0, E, 0, nullptr);

    // ---- layer 1 (relu folded into GEMM prologue; skip+messages -> d_out) ----
    k_init_nd<<<(n * 2 + 255) / 256, 256>>>(n * 2);
    k_gemm_mma<<<gb, 256, GSM_TOTAL>>>(nullptr, 0, 1, n, Wq1, bq1, Wk1, bk1, Wv1, bv1, Ws1, bs1, out);
    k_edge_alpha<<<eb, 256>>>(src, dst, eattr, We1, E);
    k_edge_exp<<<xb, 256>>>(dst, E);
    k_edge_msg<<<eb, 256>>>(src, dst, eattr, We1, E, 1, out);

    // ---- pooling + MLP head ----
    k_init_pool<<<(GG * DD + 255) / 256, 256>>>();
    k_pool<<<(n + 7) / 8, 256>>>(out, batch, n);
    k_mlp<<<GG, 128>>>(W1, b1, W2, b2, W3, b3, out, n);
}

// round 5
// speedup vs baseline: 1.6668x; 1.3342x over previous
#include <cuda_runtime.h>
#include <cuda_bf16.h>
#include <math.h>
#include <stdint.h>

#define NN 50000
#define EE 800000
#define GG 512
#define DD 128

// ---------------- scratch (device globals; no allocations) ----------------
__device__ float d_Q[NN * DD];
__device__ float d_Kf[NN * DD];
__device__ float d_Vf[NN * DD];
__device__ float d_H[NN * DD];       // layer-0 output / layer-1 input
__device__ float d_GSUM[GG * DD];
__device__ float d_GCNT[GG];
// CSR (by dst)
__device__ int   d_cnt[NN];          // counts, then cursor
__device__ int   d_rowstart[NN + 1];
__device__ int   d_psrc[EE];
__device__ float d_pea[EE];

// ---------------- helpers ----------------
__device__ __forceinline__ uint32_t smem_u32(const void* p) {
    uint32_t a;
    asm("{ .reg .u64 t; cvta.to.shared.u64 t, %1; cvt.u32.u64 %0, t; }" : "=r"(a) : "l"(p));
    return a;
}

#define LDSM_X4(r, addr)                                                      \
    asm volatile("ldmatrix.sync.aligned.m8n8.x4.shared.b16 {%0,%1,%2,%3}, [%4];" \
                 : "=r"((r)[0]), "=r"((r)[1]), "=r"((r)[2]), "=r"((r)[3])     \
                 : "r"(addr))

__device__ __forceinline__ void mma16816(float* c, const uint32_t* a,
                                         uint32_t b0, uint32_t b1) {
    asm volatile(
        "mma.sync.aligned.m16n8k16.row.col.f32.bf16.bf16.f32 "
        "{%0,%1,%2,%3}, {%4,%5,%6,%7}, {%8,%9}, {%0,%1,%2,%3};"
        : "+f"(c[0]), "+f"(c[1]), "+f"(c[2]), "+f"(c[3])
        : "r"(a[0]), "r"(a[1]), "r"(a[2]), "r"(a[3]), "r"(b0), "r"(b1));
}

// ---------------- tensor-core GEMM via mma.sync (bf16 3-split) ----------------
#define ROWB 272
#define SA_HI 0
#define SA_LO (SA_HI + 128 * ROWB)
#define SW_HI (SA_LO + 128 * ROWB)
#define SW_LO (SW_HI + 128 * ROWB)
#define SBIAS (SW_LO + 128 * ROWB)
#define GSM_TOTAL (SBIAS + 2048)

__global__ void __launch_bounds__(256, 1)
k_gemm_mma(const float* __restrict__ Xext, int use_ext, int relu_in, int n,
           const float* __restrict__ Wq, const float* __restrict__ bq,
           const float* __restrict__ Wk, const float* __restrict__ bk,
           const float* __restrict__ Wv, const float* __restrict__ bv,
           const float* __restrict__ Wsk, const float* __restrict__ bsk,
           float* __restrict__ Yskip) {
    extern __shared__ char smem[];
    const uint32_t sb = smem_u32(smem);
    const int tid = threadIdx.x;
    const int wid = tid >> 5;
    const int lane = tid & 31;
    const int row0 = blockIdx.x * 128;
    const float* X = use_ext ? Xext : d_H;
    float* s_bias = (float*)(smem + SBIAS);

    if (tid < 128) {
        s_bias[tid]       = bq[tid];
        s_bias[128 + tid] = bk[tid];
        s_bias[256 + tid] = bv[tid];
        s_bias[384 + tid] = bsk[tid];
    }

    // ---- A fill: fp32 -> bf16 hi/lo ----
    for (int idx = tid; idx < 128 * 64; idx += 256) {
        int r = idx >> 6, p = idx & 63;
        int row = row0 + r;
        float2 v = make_float2(0.f, 0.f);
        if (row < n) v = ((const float2*)X)[(long)row * 64 + p];
        if (relu_in) { v.x = fmaxf(v.x, 0.f); v.y = fmaxf(v.y, 0.f); }
        __nv_bfloat16 h0 = __float2bfloat16(v.x);
        __nv_bfloat16 h1 = __float2bfloat16(v.y);
        __nv_bfloat16 l0 = __float2bfloat16(v.x - __bfloat162float(h0));
        __nv_bfloat16 l1 = __float2bfloat16(v.y - __bfloat162float(h1));
        __nv_bfloat162 hh; hh.x = h0; hh.y = h1;
        __nv_bfloat162 ll; ll.x = l0; ll.y = l1;
        *(__nv_bfloat162*)(smem + SA_HI + r * ROWB + p * 4) = hh;
        *(__nv_bfloat162*)(smem + SA_LO + r * ROWB + p * 4) = ll;
    }
    __syncthreads();

    const int wm = wid & 3;
    const int wn = wid >> 2;
    const int a_row = wm * 32 + (lane & 15);
    const int a_colb = ((lane >> 4) * 8) * 2;
    const int b_row_in_q = ((lane >> 4) & 1) * 8 + (lane & 7);
    const int b_colb = (((lane >> 3) & 1) * 8) * 2;

    const float* Wm_[4] = {Wq, Wk, Wv, Wsk};
    float* Y_[4] = {d_Q, d_Kf, d_Vf, Yskip ? Yskip : d_H};

    for (int m = 0; m < 4; m++) {
        const float* Wm = Wm_[m];
        for (int idx = tid; idx < 128 * 64; idx += 256) {
            int o = idx >> 6, p = idx & 63;
            float2 v = ((const float2*)Wm)[(long)o * 64 + p];
            __nv_bfloat16 h0 = __float2bfloat16(v.x);
            __nv_bfloat16 h1 = __float2bfloat16(v.y);
            __nv_bfloat16 l0 = __float2bfloat16(v.x - __bfloat162float(h0));
            __nv_bfloat16 l1 = __float2bfloat16(v.y - __bfloat162float(h1));
            __nv_bfloat162 hh; hh.x = h0; hh.y = h1;
            __nv_bfloat162 ll; ll.x = l0; ll.y = l1;
            *(__nv_bfloat162*)(smem + SW_HI + o * ROWB + p * 4) = hh;
            *(__nv_bfloat162*)(smem + SW_LO + o * ROWB + p * 4) = ll;
        }
        __syncthreads();

        float acc[2][8][4];
#pragma unroll
        for (int i = 0; i < 2; i++)
#pragma unroll
            for (int j = 0; j < 8; j++)
#pragma unroll
                for (int c = 0; c < 4; c++) acc[i][j][c] = 0.f;

#pragma unroll
        for (int split = 0; split < 3; split++) {
            uint32_t Ab = sb + ((split == 2) ? SA_LO : SA_HI);
            uint32_t Bb = sb + ((split == 1) ? SW_LO : SW_HI);
#pragma unroll
            for (int ks = 0; ks < 8; ks++) {
                uint32_t a0[4], a1[4];
                uint32_t aaddr = Ab + a_row * ROWB + ks * 32 + a_colb;
                LDSM_X4(a0, aaddr);
                LDSM_X4(a1, aaddr + 16 * ROWB);
#pragma unroll
                for (int q = 0; q < 4; q++) {
                    uint32_t b[4];
                    uint32_t baddr = Bb + (wn * 64 + q * 16 + b_row_in_q) * ROWB
                                     + ks * 32 + b_colb;
                    LDSM_X4(b, baddr);
                    mma16816(acc[0][2 * q],     a0, b[0], b[1]);
                    mma16816(acc[0][2 * q + 1], a0, b[2], b[3]);
                    mma16816(acc[1][2 * q],     a1, b[0], b[1]);
                    mma16816(acc[1][2 * q + 1], a1, b[2], b[3]);
                }
            }
        }

        float* Y = Y_[m];
#pragma unroll
        for (int tm = 0; tm < 2; tm++) {
#pragma unroll
            for (int tn = 0; tn < 8; tn++) {
                int col = wn * 64 + tn * 8 + (lane & 3) * 2;
                float bx = s_bias[m * 128 + col];
                float by = s_bias[m * 128 + col + 1];
                int r1 = row0 + wm * 32 + tm * 16 + (lane >> 2);
                if (r1 < n) {
                    float2 o1 = make_float2(acc[tm][tn][0] + bx, acc[tm][tn][1] + by);
                    *(float2*)&Y[(long)r1 * 128 + col] = o1;
                }
                int r2 = r1 + 8;
                if (r2 < n) {
                    float2 o2 = make_float2(acc[tm][tn][2] + bx, acc[tm][tn][3] + by);
                    *(float2*)&Y[(long)r2 * 128 + col] = o2;
                }
            }
        }
        __syncthreads();
    }
}

// ---------------- CSR build ----------------
__global__ void k_zero_cnt(int n) {
    int i = blockIdx.x * blockDim.x + threadIdx.x;
    if (i < n) d_cnt[i] = 0;
}

__global__ void k_hist(const int* __restrict__ dst, int E) {
    int e = blockIdx.x * blockDim.x + threadIdx.x;
    if (e < E) atomicAdd(&d_cnt[dst[e]], 1);
}

// single-block exclusive scan of d_cnt -> d_rowstart; d_cnt becomes cursor
__global__ void k_scan(int n) {
    __shared__ int wsum[32];
    int t = threadIdx.x;
    int per = (n + 1023) / 1024;
    int begin = t * per;
    int end = min(begin + per, n);
    int s = 0;
    for (int i = begin; i < end; i++) s += d_cnt[i];
    int lane = t & 31, w = t >> 5;
    int v = s;
#pragma unroll
    for (int o = 1; o < 32; o <<= 1) {
        int u = __shfl_up_sync(0xffffffffu, v, o);
        if (lane >= o) v += u;
    }
    if (lane == 31) wsum[w] = v;
    __syncthreads();
    if (w == 0) {
        int ws = wsum[lane];
#pragma unroll
        for (int o = 1; o < 32; o <<= 1) {
            int u = __shfl_up_sync(0xffffffffu, ws, o);
            if (lane >= o) ws += u;
        }
        wsum[lane] = ws;   // inclusive
    }
    __syncthreads();
    int excl = v - s + (w > 0 ? wsum[w - 1] : 0);
    int run = excl;
    for (int i = begin; i < end; i++) {
        int c = d_cnt[i];
        d_rowstart[i] = run;
        d_cnt[i] = run;     // cursor
        run += c;
    }
    if (t == 0) d_rowstart[n] = wsum[31];
}

__global__ void k_fill(const int* __restrict__ src, const int* __restrict__ dst,
                       const float* __restrict__ ea, int E) {
    int e = blockIdx.x * blockDim.x + threadIdx.x;
    if (e >= E) return;
    int d = dst[e];
    int pos = atomicAdd(&d_cnt[d], 1);
    d_psrc[pos] = src[e];
    d_pea[pos] = ea[e];
}

// ---------------- fused edge kernel: single-pass softmax + aggregate ----------------
// warp per dst node; lanes 0-15 = head 0 (4 ch each), 16-31 = head 1.
__global__ void k_edge_fused(const float* __restrict__ We, int n,
                             int use_dout, float* __restrict__ dout,
                             const int* __restrict__ batch, int do_pool) {
    int node = blockIdx.x * 8 + (threadIdx.x >> 5);
    if (node >= n) return;
    int lane = threadIdx.x & 31;

    float4 we4 = __ldg((const float4*)We + lane);
    float4 q4 = *((const float4*)&d_Q[(long)node * DD] + lane);
    int p0 = d_rowstart[node];
    int p1 = d_rowstart[node + 1];

    float ax = 0.f, ay = 0.f, az = 0.f, aw = 0.f;
    float den = 0.f;

    for (int p = p0; p < p1; p++) {
        int s = __ldg(&d_psrc[p]);
        float ea = __ldg(&d_pea[p]);
        float4 k4 = __ldg((const float4*)&d_Kf[(long)s * DD] + lane);
        float t = q4.x * (k4.x + ea * we4.x) + q4.y * (k4.y + ea * we4.y) +
                  q4.z * (k4.z + ea * we4.z) + q4.w * (k4.w + ea * we4.w);
        t += __shfl_xor_sync(0xffffffffu, t, 8);
        t += __shfl_xor_sync(0xffffffffu, t, 4);
        t += __shfl_xor_sync(0xffffffffu, t, 2);
        t += __shfl_xor_sync(0xffffffffu, t, 1);
        float ex = __expf(t * 0.125f);          // no-max softmax (shift-invariant)
        float4 v4 = __ldg((const float4*)&d_Vf[(long)s * DD] + lane);
        ax += ex * (v4.x + ea * we4.x);
        ay += ex * (v4.y + ea * we4.y);
        az += ex * (v4.z + ea * we4.z);
        aw += ex * (v4.w + ea * we4.w);
        den += ex;
    }

    float inv = 1.f / (den + 1e-16f);
    float* out = use_dout ? dout : d_H;
    float4* op = (float4*)&out[(long)node * DD] + lane;
    float4 o = *op;                              // skip written by GEMM
    o.x += ax * inv; o.y += ay * inv; o.z += az * inv; o.w += aw * inv;
    *op = o;

    if (do_pool) {
        int g = __ldg(&batch[node]);
        float* pp = &d_GSUM[(long)g * DD + lane * 4];
        asm volatile("red.global.add.v4.f32 [%0], {%1,%2,%3,%4};"
                     :: "l"(pp), "f"(o.x), "f"(o.y), "f"(o.z), "f"(o.w)
                     : "memory");
        if (lane == 0) atomicAdd(&d_GCNT[g], 1.0f);
    }
}

// ---------------- init + MLP head ----------------
__global__ void k_init_pool() {
    int i = blockIdx.x * blockDim.x + threadIdx.x;
    if (i < GG * DD) d_GSUM[i] = 0.0f;
    if (i < GG) d_GCNT[i] = 0.0f;
}

__global__ void k_mlp(const float* __restrict__ W1, const float* __restrict__ b1,
                      const float* __restrict__ W2, const float* __restrict__ b2,
                      const float* __restrict__ W3, const float* __restrict__ b3,
                      float* __restrict__ out, int n_nodes) {
    __shared__ float g[128];
    __shared__ float h1[64];
    __shared__ float h2[32];
    int gr = blockIdx.x;
    int t = threadIdx.x;
    float cnt = fmaxf(d_GCNT[gr], 1.0f);
    if (t < 128) g[t] = d_GSUM[gr * 128 + t] / cnt;
    __syncthreads();
    if (t < 64) {
        float s = b1[t];
        for (int k = 0; k < 128; k++) s += W1[t * 128 + k] * g[k];
        h1[t] = fmaxf(s, 0.0f);
    }
    __syncthreads();
    if (t < 32) {
        float s = b2[t];
        for (int k = 0; k < 64; k++) s += W2[t * 64 + k] * h1[k];
        h2[t] = fmaxf(s, 0.0f);
    }
    __syncthreads();
    if (t < 16) {
        float s = b3[t];
        for (int k = 0; k < 32; k++) s += W3[t * 32 + k] * h2[k];
        out[(long)n_nodes * 128 + gr * 16 + t] = s;
    }
}

// ---------------- launcher ----------------
extern "C" void kernel_launch(void* const* d_in, const int* in_sizes, int n_in,
                              void* d_out, int out_size) {
    const float* x      = (const float*)d_in[0];
    const int*   ei     = (const int*)d_in[1];
    const int*   batch  = (const int*)d_in[2];
    const float* eattr  = (const float*)d_in[3];

    const float* Wq0 = (const float*)d_in[4];
    const float* bq0 = (const float*)d_in[5];
    const float* Wk0 = (const float*)d_in[6];
    const float* bk0 = (const float*)d_in[7];
    const float* Wv0 = (const float*)d_in[8];
    const float* bv0 = (const float*)d_in[9];
    const float* We0 = (const float*)d_in[10];
    const float* Ws0 = (const float*)d_in[11];
    const float* bs0 = (const float*)d_in[12];

    const float* Wq1 = (const float*)d_in[13];
    const float* bq1 = (const float*)d_in[14];
    const float* Wk1 = (const float*)d_in[15];
    const float* bk1 = (const float*)d_in[16];
    const float* Wv1 = (const float*)d_in[17];
    const float* bv1 = (const float*)d_in[18];
    const float* We1 = (const float*)d_in[19];
    const float* Ws1 = (const float*)d_in[20];
    const float* bs1 = (const float*)d_in[21];

    const float* W1 = (const float*)d_in[22];
    const float* b1 = (const float*)d_in[23];
    const float* W2 = (const float*)d_in[24];
    const float* b2 = (const float*)d_in[25];
    const float* W3 = (const float*)d_in[26];
    const float* b3 = (const float*)d_in[27];

    int n = in_sizes[2];        // num nodes
    int E = in_sizes[3];        // num edges
    float* out = (float*)d_out;

    cudaFuncSetAttribute(k_gemm_mma, cudaFuncAttributeMaxDynamicSharedMemorySize, GSM_TOTAL);

    const int* src = ei;
    const int* dst = ei + E;

    int gb = (n + 127) / 128;
    int nb8 = (n + 7) / 8;

    // ---- CSR build (once; reused by both layers) ----
    k_zero_cnt<<<(n + 255) / 256, 256>>>(n);
    k_hist<<<(E + 255) / 256, 256>>>(dst, E);
    k_scan<<<1, 1024>>>(n);
    k_fill<<<(E + 255) / 256, 256>>>(src, dst, eattr, E);

    k_init_pool<<<(GG * DD + 255) / 256, 256>>>();

    // ---- layer 0 ----
    k_gemm_mma<<<gb, 256, GSM_TOTAL>>>(x, 1, 0, n, Wq0, bq0, Wk0, bk0, Wv0, bv0, Ws0, bs0, nullptr);
    k_edge_fused<<<nb8, 256>>>(We0, n, 0, nullptr, nullptr, 0);

    // ---- layer 1 (relu folded into GEMM prologue; pool folded into edge kernel) ----
    k_gemm_mma<<<gb, 256, GSM_TOTAL>>>(nullptr, 0, 1, n, Wq1, bq1, Wk1, bk1, Wv1, bv1, Ws1, bs1, out);
    k_edge_fused<<<nb8, 256>>>(We1, n, 1, out, batch, 1);

    // ---- MLP head ----
    k_mlp<<<GG, 128>>>(W1, b1, W2, b2, W3, b3, out, n);
}

// round 6
// speedup vs baseline: 2.0228x; 1.2136x over previous
#include <cuda_runtime.h>
#include <cuda_bf16.h>
#include <math.h>
#include <stdint.h>

#define NN 50000
#define EE 800000
#define GG 512
#define DD 128

// ---------------- scratch (device globals; no allocations) ----------------
__device__ float d_Q[NN * DD];
__device__ float d_Kf[NN * DD];
__device__ float d_Vf[NN * DD];
__device__ float d_H[NN * DD];       // layer-0 output / layer-1 input
__device__ float d_GSUM[GG * DD];
__device__ float d_GCNT[GG];
// CSR (by dst)
__device__ int   d_cnt[NN];          // counts, then cursor
__device__ int   d_rowstart[NN + 1];
__device__ int   d_psrc[EE];
__device__ float d_pea[EE];
// pre-converted weights: 8 mats (layer0 q,k,v,skip; layer1 q,k,v,skip)
__device__ uint32_t d_WH[8][8192];   // bf16x2 hi, [o][pair]
__device__ uint32_t d_WL[8][8192];   // bf16x2 lo

// ---------------- helpers ----------------
__device__ __forceinline__ uint32_t smem_u32(const void* p) {
    uint32_t a;
    asm("{ .reg .u64 t; cvta.to.shared.u64 t, %1; cvt.u32.u64 %0, t; }" : "=r"(a) : "l"(p));
    return a;
}

#define LDSM_X4(r, addr)                                                      \
    asm volatile("ldmatrix.sync.aligned.m8n8.x4.shared.b16 {%0,%1,%2,%3}, [%4];" \
                 : "=r"((r)[0]), "=r"((r)[1]), "=r"((r)[2]), "=r"((r)[3])     \
                 : "r"(addr))

__device__ __forceinline__ void mma16816(float* c, const uint32_t* a,
                                         uint32_t b0, uint32_t b1) {
    asm volatile(
        "mma.sync.aligned.m16n8k16.row.col.f32.bf16.bf16.f32 "
        "{%0,%1,%2,%3}, {%4,%5,%6,%7}, {%8,%9}, {%0,%1,%2,%3};"
        : "+f"(c[0]), "+f"(c[1]), "+f"(c[2]), "+f"(c[3])
        : "r"(a[0]), "r"(a[1]), "r"(a[2]), "r"(a[3]), "r"(b0), "r"(b1));
}

// ---------------- weight pre-conversion: fp32 -> bf16 hi/lo ----------------
__global__ void k_wconv(const float* __restrict__ w0, const float* __restrict__ w1,
                        const float* __restrict__ w2, const float* __restrict__ w3,
                        const float* __restrict__ w4, const float* __restrict__ w5,
                        const float* __restrict__ w6, const float* __restrict__ w7) {
    int idx = blockIdx.x * 256 + threadIdx.x;   // 0..65535
    int m = idx >> 13, p = idx & 8191;
    const float* ws[8] = {w0, w1, w2, w3, w4, w5, w6, w7};
    float2 v = ((const float2*)ws[m])[p];
    __nv_bfloat162 hh;
    hh.x = __float2bfloat16(v.x);
    hh.y = __float2bfloat16(v.y);
    __nv_bfloat162 ll;
    ll.x = __float2bfloat16(v.x - __bfloat162float(hh.x));
    ll.y = __float2bfloat16(v.y - __bfloat162float(hh.y));
    d_WH[m][p] = *(uint32_t*)&hh;
    d_WL[m][p] = *(uint32_t*)&ll;
}

// ---------------- tensor-core GEMM (bf16 3-split), 64-row tiles, 2 CTA/SM ---
#define ROWB 272
#define SA_HI 0
#define SA_LO (SA_HI + 64 * ROWB)        // 17408
#define SW_HI (SA_LO + 64 * ROWB)        // 34816
#define SW_LO (SW_HI + 128 * ROWB)       // 69632
#define SBIAS (SW_LO + 128 * ROWB)       // 104448
#define GSM_TOTAL (SBIAS + 2048)         // 106496

__global__ void __launch_bounds__(256, 2)
k_gemm_mma(const float* __restrict__ Xext, int use_ext, int relu_in, int n,
           int wbase,
           const float* __restrict__ bq, const float* __restrict__ bk,
           const float* __restrict__ bv, const float* __restrict__ bsk,
           float* __restrict__ Yskip) {
    extern __shared__ char smem[];
    const uint32_t sb = smem_u32(smem);
    const int tid = threadIdx.x;
    const int wid = tid >> 5;
    const int lane = tid & 31;
    const int row0 = blockIdx.x * 64;
    const float* X = use_ext ? Xext : d_H;
    float* s_bias = (float*)(smem + SBIAS);

    if (tid < 128) {
        s_bias[tid]       = bq[tid];
        s_bias[128 + tid] = bk[tid];
        s_bias[256 + tid] = bv[tid];
        s_bias[384 + tid] = bsk[tid];
    }

    // ---- A fill: fp32 -> bf16 hi/lo (64 rows x 128 cols) ----
    for (int idx = tid; idx < 64 * 32; idx += 256) {
        int r = idx >> 5, c = idx & 31;          // c: float4 index
        int row = row0 + r;
        float4 v = make_float4(0.f, 0.f, 0.f, 0.f);
        if (row < n) v = ((const float4*)X)[(long)row * 32 + c];
        if (relu_in) {
            v.x = fmaxf(v.x, 0.f); v.y = fmaxf(v.y, 0.f);
            v.z = fmaxf(v.z, 0.f); v.w = fmaxf(v.w, 0.f);
        }
        __nv_bfloat162 h01, h23, l01, l23;
        h01.x = __float2bfloat16(v.x); h01.y = __float2bfloat16(v.y);
        h23.x = __float2bfloat16(v.z); h23.y = __float2bfloat16(v.w);
        l01.x = __float2bfloat16(v.x - __bfloat162float(h01.x));
        l01.y = __float2bfloat16(v.y - __bfloat162float(h01.y));
        l23.x = __float2bfloat16(v.z - __bfloat162float(h23.x));
        l23.y = __float2bfloat16(v.w - __bfloat162float(h23.y));
        uint2 uh; uh.x = *(uint32_t*)&h01; uh.y = *(uint32_t*)&h23;
        uint2 ul; ul.x = *(uint32_t*)&l01; ul.y = *(uint32_t*)&l23;
        *(uint2*)(smem + SA_HI + r * ROWB + c * 8) = uh;
        *(uint2*)(smem + SA_LO + r * ROWB + c * 8) = ul;
    }
    __syncthreads();

    const int wm = wid & 1;                 // row half (32 rows)
    const int wn = wid >> 1;                // col group (32 cols)
    const int a_row = wm * 32 + (lane & 15);
    const int a_colb = (lane >> 4) * 16;
    const int b_row_in_q = ((lane >> 4) & 1) * 8 + (lane & 7);
    const int b_colb = ((lane >> 3) & 1) * 16;

    float* Y_[4] = {d_Q, d_Kf, d_Vf, Yskip ? Yskip : d_H};

    for (int m = 0; m < 4; m++) {
        // ---- W fill: plain bf16 copy from pre-converted globals ----
        const uint32_t* WH = d_WH[wbase + m];
        const uint32_t* WL = d_WL[wbase + m];
        for (int idx = tid; idx < 2048; idx += 256) {
            int o = idx >> 4, c = idx & 15;      // c: uint4 (16B) index
            uint4 h = ((const uint4*)WH)[idx];
            uint4 l = ((const uint4*)WL)[idx];
            *(uint4*)(smem + SW_HI + o * ROWB + c * 16) = h;
            *(uint4*)(smem + SW_LO + o * ROWB + c * 16) = l;
        }
        __syncthreads();

        float acc[2][4][4];
#pragma unroll
        for (int i = 0; i < 2; i++)
#pragma unroll
            for (int j = 0; j < 4; j++)
#pragma unroll
                for (int c = 0; c < 4; c++) acc[i][j][c] = 0.f;

        // 3 splits: (Ahi,Whi), (Ahi,Wlo), (Alo,Whi)
#pragma unroll
        for (int split = 0; split < 3; split++) {
            uint32_t Ab = sb + ((split == 2) ? SA_LO : SA_HI);
            uint32_t Bb = sb + ((split == 1) ? SW_LO : SW_HI);
#pragma unroll
            for (int ks = 0; ks < 8; ks++) {
                uint32_t a0[4], a1[4];
                uint32_t aaddr = Ab + a_row * ROWB + ks * 32 + a_colb;
                LDSM_X4(a0, aaddr);
                LDSM_X4(a1, aaddr + 16 * ROWB);
#pragma unroll
                for (int q = 0; q < 2; q++) {
                    uint32_t b[4];
                    uint32_t baddr = Bb + (wn * 32 + q * 16 + b_row_in_q) * ROWB
                                     + ks * 32 + b_colb;
                    LDSM_X4(b, baddr);
                    mma16816(acc[0][2 * q],     a0, b[0], b[1]);
                    mma16816(acc[0][2 * q + 1], a0, b[2], b[3]);
                    mma16816(acc[1][2 * q],     a1, b[0], b[1]);
                    mma16816(acc[1][2 * q + 1], a1, b[2], b[3]);
                }
            }
        }

        // ---- epilogue: acc + bias -> global ----
        float* Y = Y_[m];
#pragma unroll
        for (int tm = 0; tm < 2; tm++) {
#pragma unroll
            for (int tn = 0; tn < 4; tn++) {
                int col = wn * 32 + tn * 8 + (lane & 3) * 2;
                float bx = s_bias[m * 128 + col];
                float by = s_bias[m * 128 + col + 1];
                int r1 = row0 + wm * 32 + tm * 16 + (lane >> 2);
                if (r1 < n) {
                    float2 o1 = make_float2(acc[tm][tn][0] + bx, acc[tm][tn][1] + by);
                    *(float2*)&Y[(long)r1 * 128 + col] = o1;
                }
                int r2 = r1 + 8;
                if (r2 < n) {
                    float2 o2 = make_float2(acc[tm][tn][2] + bx, acc[tm][tn][3] + by);
                    *(float2*)&Y[(long)r2 * 128 + col] = o2;
                }
            }
        }
        __syncthreads();
    }
}

// ---------------- CSR build + init ----------------
__global__ void k_init_all(int n) {
    int i = blockIdx.x * blockDim.x + threadIdx.x;
    if (i < n) d_cnt[i] = 0;
    if (i < GG * DD) d_GSUM[i] = 0.0f;
    if (i < GG) d_GCNT[i] = 0.0f;
}

__global__ void k_hist(const int* __restrict__ dst, int E) {
    int e = blockIdx.x * blockDim.x + threadIdx.x;
    if (e < E) atomicAdd(&d_cnt[dst[e]], 1);
}

// single-block exclusive scan of d_cnt -> d_rowstart; d_cnt becomes cursor
__global__ void k_scan(int n) {
    __shared__ int wsum[32];
    int t = threadIdx.x;
    int per = (n + 1023) / 1024;
    int begin = t * per;
    int end = min(begin + per, n);
    int s = 0;
    for (int i = begin; i < end; i++) s += d_cnt[i];
    int lane = t & 31, w = t >> 5;
    int v = s;
#pragma unroll
    for (int o = 1; o < 32; o <<= 1) {
        int u = __shfl_up_sync(0xffffffffu, v, o);
        if (lane >= o) v += u;
    }
    if (lane == 31) wsum[w] = v;
    __syncthreads();
    if (w == 0) {
        int ws = wsum[lane];
#pragma unroll
        for (int o = 1; o < 32; o <<= 1) {
            int u = __shfl_up_sync(0xffffffffu, ws, o);
            if (lane >= o) ws += u;
        }
        wsum[lane] = ws;   // inclusive
    }
    __syncthreads();
    int excl = v - s + (w > 0 ? wsum[w - 1] : 0);
    int run = excl;
    for (int i = begin; i < end; i++) {
        int c = d_cnt[i];
        d_rowstart[i] = run;
        d_cnt[i] = run;     // cursor
        run += c;
    }
    if (t == 0) d_rowstart[n] = wsum[31];
}

__global__ void k_fill(const int* __restrict__ src, const int* __restrict__ dst,
                       const float* __restrict__ ea, int E) {
    int e = blockIdx.x * blockDim.x + threadIdx.x;
    if (e >= E) return;
    int d = dst[e];
    int pos = atomicAdd(&d_cnt[d], 1);
    d_psrc[pos] = src[e];
    d_pea[pos] = ea[e];
}

// ---------------- fused edge kernel: single-pass softmax + aggregate ----------------
__global__ void k_edge_fused(const float* __restrict__ We, int n,
                             int use_dout, float* __restrict__ dout,
                             const int* __restrict__ batch, int do_pool) {
    int node = blockIdx.x * 8 + (threadIdx.x >> 5);
    if (node >= n) return;
    int lane = threadIdx.x & 31;

    float4 we4 = __ldg((const float4*)We + lane);
    float4 q4 = *((const float4*)&d_Q[(long)node * DD] + lane);
    int p0 = d_rowstart[node];
    int p1 = d_rowstart[node + 1];

    float ax = 0.f, ay = 0.f, az = 0.f, aw = 0.f;
    float den = 0.f;

    for (int p = p0; p < p1; p++) {
        int s = __ldg(&d_psrc[p]);
        float ea = __ldg(&d_pea[p]);
        float4 k4 = __ldg((const float4*)&d_Kf[(long)s * DD] + lane);
        float t = q4.x * (k4.x + ea * we4.x) + q4.y * (k4.y + ea * we4.y) +
                  q4.z * (k4.z + ea * we4.z) + q4.w * (k4.w + ea * we4.w);
        t += __shfl_xor_sync(0xffffffffu, t, 8);
        t += __shfl_xor_sync(0xffffffffu, t, 4);
        t += __shfl_xor_sync(0xffffffffu, t, 2);
        t += __shfl_xor_sync(0xffffffffu, t, 1);
        float ex = __expf(t * 0.125f);          // no-max softmax (shift-invariant)
        float4 v4 = __ldg((const float4*)&d_Vf[(long)s * DD] + lane);
        ax += ex * (v4.x + ea * we4.x);
        ay += ex * (v4.y + ea * we4.y);
        az += ex * (v4.z + ea * we4.z);
        aw += ex * (v4.w + ea * we4.w);
        den += ex;
    }

    float inv = 1.f / (den + 1e-16f);
    float* out = use_dout ? dout : d_H;
    float4* op = (float4*)&out[(long)node * DD] + lane;
    float4 o = *op;                              // skip written by GEMM
    o.x += ax * inv; o.y += ay * inv; o.z += az * inv; o.w += aw * inv;
    *op = o;

    if (do_pool) {
        int g = __ldg(&batch[node]);
        float* pp = &d_GSUM[(long)g * DD + lane * 4];
        asm volatile("red.global.add.v4.f32 [%0], {%1,%2,%3,%4};"
                     :: "l"(pp), "f"(o.x), "f"(o.y), "f"(o.z), "f"(o.w)
                     : "memory");
        if (lane == 0) atomicAdd(&d_GCNT[g], 1.0f);
    }
}

// ---------------- MLP head ----------------
__global__ void k_mlp(const float* __restrict__ W1, const float* __restrict__ b1,
                      const float* __restrict__ W2, const float* __restrict__ b2,
                      const float* __restrict__ W3, const float* __restrict__ b3,
                      float* __restrict__ out, int n_nodes) {
    __shared__ float g[128];
    __shared__ float h1[64];
    __shared__ float h2[32];
    int gr = blockIdx.x;
    int t = threadIdx.x;
    float cnt = fmaxf(d_GCNT[gr], 1.0f);
    if (t < 128) g[t] = d_GSUM[gr * 128 + t] / cnt;
    __syncthreads();
    if (t < 64) {
        float s = b1[t];
        for (int k = 0; k < 128; k++) s += W1[t * 128 + k] * g[k];
        h1[t] = fmaxf(s, 0.0f);
    }
    __syncthreads();
    if (t < 32) {
        float s = b2[t];
        for (int k = 0; k < 64; k++) s += W2[t * 64 + k] * h1[k];
        h2[t] = fmaxf(s, 0.0f);
    }
    __syncthreads();
    if (t < 16) {
        float s = b3[t];
        for (int k = 0; k < 32; k++) s += W3[t * 32 + k] * h2[k];
        out[(long)n_nodes * 128 + gr * 16 + t] = s;
    }
}

// ---------------- launcher ----------------
extern "C" void kernel_launch(void* const* d_in, const int* in_sizes, int n_in,
                              void* d_out, int out_size) {
    const float* x      = (const float*)d_in[0];
    const int*   ei     = (const int*)d_in[1];
    const int*   batch  = (const int*)d_in[2];
    const float* eattr  = (const float*)d_in[3];

    const float* Wq0 = (const float*)d_in[4];
    const float* bq0 = (const float*)d_in[5];
    const float* Wk0 = (const float*)d_in[6];
    const float* bk0 = (const float*)d_in[7];
    const float* Wv0 = (const float*)d_in[8];
    const float* bv0 = (const float*)d_in[9];
    const float* We0 = (const float*)d_in[10];
    const float* Ws0 = (const float*)d_in[11];
    const float* bs0 = (const float*)d_in[12];

    const float* Wq1 = (const float*)d_in[13];
    const float* bq1 = (const float*)d_in[14];
    const float* Wk1 = (const float*)d_in[15];
    const float* bk1 = (const float*)d_in[16];
    const float* Wv1 = (const float*)d_in[17];
    const float* bv1 = (const float*)d_in[18];
    const float* We1 = (const float*)d_in[19];
    const float* Ws1 = (const float*)d_in[20];
    const float* bs1 = (const float*)d_in[21];

    const float* W1 = (const float*)d_in[22];
    const float* b1 = (const float*)d_in[23];
    const float* W2 = (const float*)d_in[24];
    const float* b2 = (const float*)d_in[25];
    const float* W3 = (const float*)d_in[26];
    const float* b3 = (const float*)d_in[27];

    int n = in_sizes[2];        // num nodes
    int E = in_sizes[3];        // num edges
    float* out = (float*)d_out;

    cudaFuncSetAttribute(k_gemm_mma, cudaFuncAttributeMaxDynamicSharedMemorySize, GSM_TOTAL);

    const int* src = ei;
    const int* dst = ei + E;

    int gb = (n + 63) / 64;
    int nb8 = (n + 7) / 8;

    // ---- weight pre-conversion (8 mats) + init + CSR build ----
    k_wconv<<<256, 256>>>(Wq0, Wk0, Wv0, Ws0, Wq1, Wk1, Wv1, Ws1);
    k_init_all<<<(GG * DD + 255) / 256, 256>>>(n);
    k_hist<<<(E + 255) / 256, 256>>>(dst, E);
    k_scan<<<1, 1024>>>(n);
    k_fill<<<(E + 255) / 256, 256>>>(src, dst, eattr, E);

    // ---- layer 0 ----
    k_gemm_mma<<<gb, 256, GSM_TOTAL>>>(x, 1, 0, n, 0, bq0, bk0, bv0, bs0, nullptr);
    k_edge_fused<<<nb8, 256>>>(We0, n, 0, nullptr, nullptr, 0);

    // ---- layer 1 (relu folded into GEMM prologue; pool folded into edge kernel) ----
    k_gemm_mma<<<gb, 256, GSM_TOTAL>>>(nullptr, 0, 1, n, 4, bq1, bk1, bv1, bs1, out);
    k_edge_fused<<<nb8, 256>>>(We1, n, 1, out, batch, 1);

    // ---- MLP head ----
    k_mlp<<<GG, 128>>>(W1, b1, W2, b2, W3, b3, out, n);
}

// round 7
// speedup vs baseline: 2.2876x; 1.1309x over previous
#include <cuda_runtime.h>
#include <cuda_bf16.h>
#include <math.h>
#include <stdint.h>

#define NN 50000
#define EE 800000
#define GG 512
#define DD 128

// ---------------- scratch (device globals; no allocations) ----------------
__device__ float d_Q[NN * DD];
__device__ float d_Kf[NN * DD];
__device__ float d_Vf[NN * DD];
__device__ float d_H[NN * DD];       // layer-0 output / layer-1 input
__device__ float d_GSUM[GG * DD];
__device__ float d_GCNT[GG];
// CSR (by dst)
__device__ int   d_cnt[NN];          // counts, then cursor
__device__ int   d_rowstart[NN + 1];
__device__ int   d_bsum[256];        // block sums for hierarchical scan
__device__ int   d_psrc[EE];
__device__ float d_pea[EE];
// pre-converted weights: 8 mats (layer0 q,k,v,skip; layer1 q,k,v,skip)
__device__ uint32_t d_WH[8][8192];   // bf16x2 hi, [o][pair]
__device__ uint32_t d_WL[8][8192];   // bf16x2 lo

// ---------------- helpers ----------------
__device__ __forceinline__ uint32_t smem_u32(const void* p) {
    uint32_t a;
    asm("{ .reg .u64 t; cvta.to.shared.u64 t, %1; cvt.u32.u64 %0, t; }" : "=r"(a) : "l"(p));
    return a;
}

#define LDSM_X4(r, addr)                                                      \
    asm volatile("ldmatrix.sync.aligned.m8n8.x4.shared.b16 {%0,%1,%2,%3}, [%4];" \
                 : "=r"((r)[0]), "=r"((r)[1]), "=r"((r)[2]), "=r"((r)[3])     \
                 : "r"(addr))

__device__ __forceinline__ void mma16816(float* c, const uint32_t* a,
                                         uint32_t b0, uint32_t b1) {
    asm volatile(
        "mma.sync.aligned.m16n8k16.row.col.f32.bf16.bf16.f32 "
        "{%0,%1,%2,%3}, {%4,%5,%6,%7}, {%8,%9}, {%0,%1,%2,%3};"
        : "+f"(c[0]), "+f"(c[1]), "+f"(c[2]), "+f"(c[3])
        : "r"(a[0]), "r"(a[1]), "r"(a[2]), "r"(a[3]), "r"(b0), "r"(b1));
}

// ---------------- weight pre-conversion: fp32 -> bf16 hi/lo ----------------
__global__ void k_wconv(const float* __restrict__ w0, const float* __restrict__ w1,
                        const float* __restrict__ w2, const float* __restrict__ w3,
                        const float* __restrict__ w4, const float* __restrict__ w5,
                        const float* __restrict__ w6, const float* __restrict__ w7) {
    int idx = blockIdx.x * 256 + threadIdx.x;   // 0..65535
    int m = idx >> 13, p = idx & 8191;
    const float* ws[8] = {w0, w1, w2, w3, w4, w5, w6, w7};
    float2 v = ((const float2*)ws[m])[p];
    __nv_bfloat162 hh;
    hh.x = __float2bfloat16(v.x);
    hh.y = __float2bfloat16(v.y);
    __nv_bfloat162 ll;
    ll.x = __float2bfloat16(v.x - __bfloat162float(hh.x));
    ll.y = __float2bfloat16(v.y - __bfloat162float(hh.y));
    d_WH[m][p] = *(uint32_t*)&hh;
    d_WL[m][p] = *(uint32_t*)&ll;
}

// ---------------- tensor-core GEMM (bf16 3-split), 64-row tiles, 2 CTA/SM ---
#define ROWB 272
#define SA_HI 0
#define SA_LO (SA_HI + 64 * ROWB)        // 17408
#define SW_HI (SA_LO + 64 * ROWB)        // 34816
#define SW_LO (SW_HI + 128 * ROWB)       // 69632
#define SBIAS (SW_LO + 128 * ROWB)       // 104448
#define GSM_TOTAL (SBIAS + 2048)         // 106496

__global__ void __launch_bounds__(256, 2)
k_gemm_mma(const float* __restrict__ Xext, int use_ext, int relu_in, int n,
           int wbase,
           const float* __restrict__ bq, const float* __restrict__ bk,
           const float* __restrict__ bv, const float* __restrict__ bsk,
           float* __restrict__ Yskip) {
    extern __shared__ char smem[];
    const uint32_t sb = smem_u32(smem);
    const int tid = threadIdx.x;
    const int wid = tid >> 5;
    const int lane = tid & 31;
    const int row0 = blockIdx.x * 64;
    const float* X = use_ext ? Xext : d_H;
    float* s_bias = (float*)(smem + SBIAS);

    if (tid < 128) {
        s_bias[tid]       = bq[tid];
        s_bias[128 + tid] = bk[tid];
        s_bias[256 + tid] = bv[tid];
        s_bias[384 + tid] = bsk[tid];
    }

    // ---- A fill: fp32 -> bf16 hi/lo (64 rows x 128 cols) ----
    for (int idx = tid; idx < 64 * 32; idx += 256) {
        int r = idx >> 5, c = idx & 31;          // c: float4 index
        int row = row0 + r;
        float4 v = make_float4(0.f, 0.f, 0.f, 0.f);
        if (row < n) v = ((const float4*)X)[(long)row * 32 + c];
        if (relu_in) {
            v.x = fmaxf(v.x, 0.f); v.y = fmaxf(v.y, 0.f);
            v.z = fmaxf(v.z, 0.f); v.w = fmaxf(v.w, 0.f);
        }
        __nv_bfloat162 h01, h23, l01, l23;
        h01.x = __float2bfloat16(v.x); h01.y = __float2bfloat16(v.y);
        h23.x = __float2bfloat16(v.z); h23.y = __float2bfloat16(v.w);
        l01.x = __float2bfloat16(v.x - __bfloat162float(h01.x));
        l01.y = __float2bfloat16(v.y - __bfloat162float(h01.y));
        l23.x = __float2bfloat16(v.z - __bfloat162float(h23.x));
        l23.y = __float2bfloat16(v.w - __bfloat162float(h23.y));
        uint2 uh; uh.x = *(uint32_t*)&h01; uh.y = *(uint32_t*)&h23;
        uint2 ul; ul.x = *(uint32_t*)&l01; ul.y = *(uint32_t*)&l23;
        *(uint2*)(smem + SA_HI + r * ROWB + c * 8) = uh;
        *(uint2*)(smem + SA_LO + r * ROWB + c * 8) = ul;
    }
    __syncthreads();

    const int wm = wid & 1;                 // row half (32 rows)
    const int wn = wid >> 1;                // col group (32 cols)
    const int a_row = wm * 32 + (lane & 15);
    const int a_colb = (lane >> 4) * 16;
    const int b_row_in_q = ((lane >> 4) & 1) * 8 + (lane & 7);
    const int b_colb = ((lane >> 3) & 1) * 16;

    float* Y_[4] = {d_Q, d_Kf, d_Vf, Yskip ? Yskip : d_H};

    for (int m = 0; m < 4; m++) {
        // ---- W fill: plain bf16 copy from pre-converted globals ----
        const uint32_t* WH = d_WH[wbase + m];
        const uint32_t* WL = d_WL[wbase + m];
        for (int idx = tid; idx < 2048; idx += 256) {
            int o = idx >> 4, c = idx & 15;      // c: uint4 (16B) index
            uint4 h = ((const uint4*)WH)[idx];
            uint4 l = ((const uint4*)WL)[idx];
            *(uint4*)(smem + SW_HI + o * ROWB + c * 16) = h;
            *(uint4*)(smem + SW_LO + o * ROWB + c * 16) = l;
        }
        __syncthreads();

        float acc[2][4][4];
#pragma unroll
        for (int i = 0; i < 2; i++)
#pragma unroll
            for (int j = 0; j < 4; j++)
#pragma unroll
                for (int c = 0; c < 4; c++) acc[i][j][c] = 0.f;

        // 3 splits: (Ahi,Whi), (Ahi,Wlo), (Alo,Whi)
#pragma unroll
        for (int split = 0; split < 3; split++) {
            uint32_t Ab = sb + ((split == 2) ? SA_LO : SA_HI);
            uint32_t Bb = sb + ((split == 1) ? SW_LO : SW_HI);
#pragma unroll
            for (int ks = 0; ks < 8; ks++) {
                uint32_t a0[4], a1[4];
                uint32_t aaddr = Ab + a_row * ROWB + ks * 32 + a_colb;
                LDSM_X4(a0, aaddr);
                LDSM_X4(a1, aaddr + 16 * ROWB);
#pragma unroll
                for (int q = 0; q < 2; q++) {
                    uint32_t b[4];
                    uint32_t baddr = Bb + (wn * 32 + q * 16 + b_row_in_q) * ROWB
                                     + ks * 32 + b_colb;
                    LDSM_X4(b, baddr);
                    mma16816(acc[0][2 * q],     a0, b[0], b[1]);
                    mma16816(acc[0][2 * q + 1], a0, b[2], b[3]);
                    mma16816(acc[1][2 * q],     a1, b[0], b[1]);
                    mma16816(acc[1][2 * q + 1], a1, b[2], b[3]);
                }
            }
        }

        // ---- epilogue: acc + bias -> global ----
        float* Y = Y_[m];
#pragma unroll
        for (int tm = 0; tm < 2; tm++) {
#pragma unroll
            for (int tn = 0; tn < 4; tn++) {
                int col = wn * 32 + tn * 8 + (lane & 3) * 2;
                float bx = s_bias[m * 128 + col];
                float by = s_bias[m * 128 + col + 1];
                int r1 = row0 + wm * 32 + tm * 16 + (lane >> 2);
                if (r1 < n) {
                    float2 o1 = make_float2(acc[tm][tn][0] + bx, acc[tm][tn][1] + by);
                    *(float2*)&Y[(long)r1 * 128 + col] = o1;
                }
                int r2 = r1 + 8;
                if (r2 < n) {
                    float2 o2 = make_float2(acc[tm][tn][2] + bx, acc[tm][tn][3] + by);
                    *(float2*)&Y[(long)r2 * 128 + col] = o2;
                }
            }
        }
        __syncthreads();
    }
}

// ---------------- CSR build + init ----------------
__global__ void k_init_all(int n) {
    int i = blockIdx.x * blockDim.x + threadIdx.x;
    if (i < n) d_cnt[i] = 0;
    if (i < GG * DD) d_GSUM[i] = 0.0f;
    if (i < GG) d_GCNT[i] = 0.0f;
}

__global__ void k_hist(const int* __restrict__ dst, int E) {
    int e = blockIdx.x * blockDim.x + threadIdx.x;
    if (e < E) atomicAdd(&d_cnt[dst[e]], 1);
}

// hierarchical scan, phase 1: per-block (256-wide) exclusive scan, coalesced
__global__ void k_scan1(int n) {
    __shared__ int wsum[8];
    int t = threadIdx.x;
    int i = blockIdx.x * 256 + t;
    int v = (i < n) ? d_cnt[i] : 0;
    int lane = t & 31, w = t >> 5;
    int x = v;
#pragma unroll
    for (int o = 1; o < 32; o <<= 1) {
        int u = __shfl_up_sync(0xffffffffu, x, o);
        if (lane >= o) x += u;
    }
    if (lane == 31) wsum[w] = x;
    __syncthreads();
    if (t < 8) {
        int ws = wsum[t];
#pragma unroll
        for (int o = 1; o < 8; o <<= 1) {
            int u = __shfl_up_sync(0x000000ffu, ws, o);
            if (t >= o) ws += u;
        }
        wsum[t] = ws;   // inclusive
    }
    __syncthreads();
    int excl = x - v + (w > 0 ? wsum[w - 1] : 0);
    if (i < n) d_rowstart[i] = excl;          // local prefix
    if (t == 255) d_bsum[blockIdx.x] = excl + v;  // block total
}

// phase 2: exclusive scan of block sums (nb <= 256), 1 block
__global__ void k_scan2(int nb) {
    __shared__ int wsum[8];
    int t = threadIdx.x;
    int v = (t < nb) ? d_bsum[t] : 0;
    int lane = t & 31, w = t >> 5;
    int x = v;
#pragma unroll
    for (int o = 1; o < 32; o <<= 1) {
        int u = __shfl_up_sync(0xffffffffu, x, o);
        if (lane >= o) x += u;
    }
    if (lane == 31) wsum[w] = x;
    __syncthreads();
    if (t < 8) {
        int ws = wsum[t];
#pragma unroll
        for (int o = 1; o < 8; o <<= 1) {
            int u = __shfl_up_sync(0x000000ffu, ws, o);
            if (t >= o) ws += u;
        }
        wsum[t] = ws;
    }
    __syncthreads();
    int excl = x - v + (w > 0 ? wsum[w - 1] : 0);
    if (t < nb) d_bsum[t] = excl;
}

// phase 3: add block offsets; init cursor; rowstart[n] = E
__global__ void k_scan3(int n, int E) {
    int i = blockIdx.x * 256 + threadIdx.x;
    if (i < n) {
        int v = d_rowstart[i] + d_bsum[blockIdx.x];
        d_rowstart[i] = v;
        d_cnt[i] = v;      // cursor for k_fill
    }
    if (i == 0) d_rowstart[n] = E;
}

__global__ void k_fill(const int* __restrict__ src, const int* __restrict__ dst,
                       const float* __restrict__ ea, int E) {
    int e = blockIdx.x * blockDim.x + threadIdx.x;
    if (e >= E) return;
    int d = dst[e];
    int pos = atomicAdd(&d_cnt[d], 1);
    d_psrc[pos] = src[e];
    d_pea[pos] = ea[e];
}

// ---------------- fused edge kernel: single-pass softmax + aggregate ----------------
__global__ void k_edge_fused(const float* __restrict__ We, int n,
                             int use_dout, float* __restrict__ dout,
                             const int* __restrict__ batch, int do_pool) {
    int node = blockIdx.x * 8 + (threadIdx.x >> 5);
    if (node >= n) return;
    int lane = threadIdx.x & 31;

    float4 we4 = __ldg((const float4*)We + lane);
    float4 q4 = *((const float4*)&d_Q[(long)node * DD] + lane);
    int p0 = d_rowstart[node];
    int p1 = d_rowstart[node + 1];

    float ax = 0.f, ay = 0.f, az = 0.f, aw = 0.f;
    float den = 0.f;

    for (int p = p0; p < p1; p++) {
        int s = __ldg(&d_psrc[p]);
        float ea = __ldg(&d_pea[p]);
        float4 k4 = __ldg((const float4*)&d_Kf[(long)s * DD] + lane);
        float t = q4.x * (k4.x + ea * we4.x) + q4.y * (k4.y + ea * we4.y) +
                  q4.z * (k4.z + ea * we4.z) + q4.w * (k4.w + ea * we4.w);
        t += __shfl_xor_sync(0xffffffffu, t, 8);
        t += __shfl_xor_sync(0xffffffffu, t, 4);
        t += __shfl_xor_sync(0xffffffffu, t, 2);
        t += __shfl_xor_sync(0xffffffffu, t, 1);
        float ex = __expf(t * 0.125f);          // no-max softmax (shift-invariant)
        float4 v4 = __ldg((const float4*)&d_Vf[(long)s * DD] + lane);
        ax += ex * (v4.x + ea * we4.x);
        ay += ex * (v4.y + ea * we4.y);
        az += ex * (v4.z + ea * we4.z);
        aw += ex * (v4.w + ea * we4.w);
        den += ex;
    }

    float inv = 1.f / (den + 1e-16f);
    float* out = use_dout ? dout : d_H;
    float4* op = (float4*)&out[(long)node * DD] + lane;
    float4 o = *op;                              // skip written by GEMM
    o.x += ax * inv; o.y += ay * inv; o.z += az * inv; o.w += aw * inv;
    *op = o;

    if (do_pool) {
        int g = __ldg(&batch[node]);
        float* pp = &d_GSUM[(long)g * DD + lane * 4];
        asm volatile("red.global.add.v4.f32 [%0], {%1,%2,%3,%4};"
                     :: "l"(pp), "f"(o.x), "f"(o.y), "f"(o.z), "f"(o.w)
                     : "memory");
        if (lane == 0) atomicAdd(&d_GCNT[g], 1.0f);
    }
}

// ---------------- MLP head ----------------
__global__ void k_mlp(const float* __restrict__ W1, const float* __restrict__ b1,
                      const float* __restrict__ W2, const float* __restrict__ b2,
                      const float* __restrict__ W3, const float* __restrict__ b3,
                      float* __restrict__ out, int n_nodes) {
    __shared__ float g[128];
    __shared__ float h1[64];
    __shared__ float h2[32];
    int gr = blockIdx.x;
    int t = threadIdx.x;
    float cnt = fmaxf(d_GCNT[gr], 1.0f);
    if (t < 128) g[t] = d_GSUM[gr * 128 + t] / cnt;
    __syncthreads();
    if (t < 64) {
        float s = b1[t];
        for (int k = 0; k < 128; k++) s += W1[t * 128 + k] * g[k];
        h1[t] = fmaxf(s, 0.0f);
    }
    __syncthreads();
    if (t < 32) {
        float s = b2[t];
        for (int k = 0; k < 64; k++) s += W2[t * 64 + k] * h1[k];
        h2[t] = fmaxf(s, 0.0f);
    }
    __syncthreads();
    if (t < 16) {
        float s = b3[t];
        for (int k = 0; k < 32; k++) s += W3[t * 32 + k] * h2[k];
        out[(long)n_nodes * 128 + gr * 16 + t] = s;
    }
}

// ---------------- launcher ----------------
extern "C" void kernel_launch(void* const* d_in, const int* in_sizes, int n_in,
                              void* d_out, int out_size) {
    const float* x      = (const float*)d_in[0];
    const int*   ei     = (const int*)d_in[1];
    const int*   batch  = (const int*)d_in[2];
    const float* eattr  = (const float*)d_in[3];

    const float* Wq0 = (const float*)d_in[4];
    const float* bq0 = (const float*)d_in[5];
    const float* Wk0 = (const float*)d_in[6];
    const float* bk0 = (const float*)d_in[7];
    const float* Wv0 = (const float*)d_in[8];
    const float* bv0 = (const float*)d_in[9];
    const float* We0 = (const float*)d_in[10];
    const float* Ws0 = (const float*)d_in[11];
    const float* bs0 = (const float*)d_in[12];

    const float* Wq1 = (const float*)d_in[13];
    const float* bq1 = (const float*)d_in[14];
    const float* Wk1 = (const float*)d_in[15];
    const float* bk1 = (const float*)d_in[16];
    const float* Wv1 = (const float*)d_in[17];
    const float* bv1 = (const float*)d_in[18];
    const float* We1 = (const float*)d_in[19];
    const float* Ws1 = (const float*)d_in[20];
    const float* bs1 = (const float*)d_in[21];

    const float* W1 = (const float*)d_in[22];
    const float* b1 = (const float*)d_in[23];
    const float* W2 = (const float*)d_in[24];
    const float* b2 = (const float*)d_in[25];
    const float* W3 = (const float*)d_in[26];
    const float* b3 = (const float*)d_in[27];

    int n = in_sizes[2];        // num nodes
    int E = in_sizes[3];        // num edges
    float* out = (float*)d_out;

    cudaFuncSetAttribute(k_gemm_mma, cudaFuncAttributeMaxDynamicSharedMemorySize, GSM_TOTAL);

    const int* src = ei;
    const int* dst = ei + E;

    int gb = (n + 63) / 64;
    int nb8 = (n + 7) / 8;
    int snb = (n + 255) / 256;       // scan blocks (<=256 required)

    // ---- weight pre-conversion (8 mats) + init + CSR build ----
    k_wconv<<<256, 256>>>(Wq0, Wk0, Wv0, Ws0, Wq1, Wk1, Wv1, Ws1);
    k_init_all<<<(GG * DD + 255) / 256, 256>>>(n);
    k_hist<<<(E + 255) / 256, 256>>>(dst, E);
    k_scan1<<<snb, 256>>>(n);
    k_scan2<<<1, 256>>>(snb);
    k_scan3<<<snb, 256>>>(n, E);
    k_fill<<<(E + 255) / 256, 256>>>(src, dst, eattr, E);

    // ---- layer 0 ----
    k_gemm_mma<<<gb, 256, GSM_TOTAL>>>(x, 1, 0, n, 0, bq0, bk0, bv0, bs0, nullptr);
    k_edge_fused<<<nb8, 256>>>(We0, n, 0, nullptr, nullptr, 0);

    // ---- layer 1 (relu folded into GEMM prologue; pool folded into edge kernel) ----
    k_gemm_mma<<<gb, 256, GSM_TOTAL>>>(nullptr, 0, 1, n, 4, bq1, bk1, bv1, bs1, out);
    k_edge_fused<<<nb8, 256>>>(We1, n, 1, out, batch, 1);

    // ---- MLP head ----
    k_mlp<<<GG, 128>>>(W1, b1, W2, b2, W3, b3, out, n);
}